// round 9
// baseline (speedup 1.0000x reference)
#include <cuda_runtime.h>
#include <math.h>
#include <string.h>

#define NPATH 11
#define DIMF  288
#define BZ    8
#define CHK   64
#define NT    128
#define UVS   8            // uv-split factor
#define CHPC  (16/UVS)     // chunks per CTA per path
#define X1S   289
#define X2S   288
#define TSTR2 66           // u64 row stride: 2*66*K mod 32 = {4,12,20} -> conflict-free

#define FMA2(d,a,b) asm("fma.rn.f32x2 %0, %1, %2, %0;" : "+l"(d) : "l"(a), "l"(b))
#define PK2(d,lo,hi) asm("mov.b64 %0, {%1, %2};" : "=l"(d) : "f"(lo), "f"(hi))
#define UPK2(lo,hi,s) asm("mov.b64 {%0, %1}, %2;" : "=f"(lo), "=f"(hi) : "l"(s))

static const int hc_l1[NPATH] = {0,1,2,0,1,1,2,0,1,2,2};
static const int hc_l2[NPATH] = {0,1,2,1,0,2,1,2,1,0,2};
static const int hc_lo[NPATH] = {0,0,0,1,1,1,1,2,2,2,2};

__device__ float g_C[NPATH][125];          // dense normalized w3j, [(i*D2+j)*K + k]
__device__ float g_part[UVS][2048*DIMF];   // scratch partials

// ---------------- host-side Wigner-3j (exact port of reference) ------------
static double hfact(int n){ double r=1.0; for(int i=2;i<=n;++i) r*=i; return r; }

static double h_su2(int j1,int m1,int j2,int m2,int j3,int m3){
  if (m1+m2 != m3) return 0.0;
  int vmin = -j1+j2+m3; if (-j1+m1 > vmin) vmin = -j1+m1; if (vmin < 0) vmin = 0;
  int vmax = j2+j3+m1; if (j3-j1+j2 < vmax) vmax = j3-j1+j2; if (j3+m3 < vmax) vmax = j3+m3;
  if (vmax < vmin) return 0.0;
  double C = sqrt((2.0*j3+1.0)
    * hfact(j3+j1-j2)*hfact(j3-j1+j2)*hfact(j1+j2-j3)*hfact(j3+m3)*hfact(j3-m3)
    / (hfact(j1+j2+j3+1)*hfact(j1-m1)*hfact(j1+m1)*hfact(j2-m2)*hfact(j2+m2)));
  double S = 0.0;
  for (int v = vmin; v <= vmax; ++v){
    double t = hfact(j2+j3+m1-v)*hfact(j1-m1+v)
             / (hfact(v)*hfact(j3-j1+j2-v)*hfact(j3+m3-v)*hfact(v+j1-j2-m3));
    S += ((v+j2+m2)&1) ? -t : t;
  }
  return C*S;
}

static void h_q(int l,int a,int b,double&re,double&im){
  double r=0.0,i=0.0; int m=a-l; const double s2=0.70710678118654752440;
  if (m<0){ if (b==l-m) r=s2; if (b==l+m) i=-s2; }
  else if (m==0){ if (b==l) r=1.0; }
  else { double s=(m&1)?-1.0:1.0; if (b==l+m) r=s*s2; if (b==l-m) i=s*s2; }
  if (l==1){ double t=r; r=i; i=-t; }       // *(-i)
  else if (l==2){ r=-r; i=-i; }             // *(-1)
  re=r; im=i;
}

static void compute_w3j_dense(float Cd[NPATH][125]){
  for (int p=0;p<NPATH;++p){
    int l1=hc_l1[p], l2=hc_l2[p], l3=hc_lo[p];
    int d1=2*l1+1, d2=2*l2+1, d3=2*l3+1;
    double cg[125]; for (int e=0;e<125;++e) cg[e]=0.0;
    for (int i=0;i<d1;++i) for (int k=0;k<d2;++k){
      int m1=i-l1, m2=k-l2;
      if (m1+m2 >= -l3 && m1+m2 <= l3)
        cg[(i*d2+k)*d3 + (l3+m1+m2)] = h_su2(l1,m1,l2,m2,l3,m1+m2);
    }
    double Cv[125]; double nrm=0.0;
    for (int jj=0;jj<d1;++jj) for (int ll=0;ll<d2;++ll) for (int mm=0;mm<d3;++mm){
      double cr=0.0;
      for (int i=0;i<d1;++i){
        double q1r,q1i; h_q(l1,i,jj,q1r,q1i);
        if (q1r==0.0 && q1i==0.0) continue;
        for (int k=0;k<d2;++k){
          double q2r,q2i; h_q(l2,k,ll,q2r,q2i);
          if (q2r==0.0 && q2i==0.0) continue;
          int n=(i-l1)+(k-l2)+l3;
          if (n<0 || n>=d3) continue;
          double g=cg[(i*d2+k)*d3+n];
          if (g==0.0) continue;
          double q3r,q3i; h_q(l3,n,mm,q3r,q3i); q3i=-q3i;
          double ar=q1r*q2r-q1i*q2i, ai=q1r*q2i+q1i*q2r;
          cr += g*(ar*q3r - ai*q3i);
        }
      }
      Cv[(jj*d2+ll)*d3+mm]=cr; nrm += cr*cr;
    }
    double inorm = 1.0/sqrt(nrm);
    for (int e=0;e<125;++e) Cd[p][e]=0.f;
    for (int e=0;e<d1*d2*d3;++e) Cd[p][e] = (float)(Cv[e]*inorm);
  }
}

// ------------------------- main kernel -------------------------------------
// T pairs: u64 holds (t[z], t[z+2]). z-pair index zp: pairs are
// zp0:(0,2) zp1:(1,3) zp2:(4,6) zp3:(5,7); build pass rp, thread zb writes zp=rp*2+zb.
template<int L1, int L2, int LO>
__device__ __forceinline__ void process_path(
    int p, int ch0, const float* __restrict__ ws,
    const float* x1s, const float* x2t,
    float* wss, unsigned long long* Tp, float* sC,
    unsigned long long* acc, int tid, int w, int zps)
{
  constexpr int D1 = 2*L1+1, D2 = 2*L2+1, K = 2*LO+1;
  constexpr int O1  = (L1==0)?0:((L1==1)?32:128);
  constexpr int O2T = (L2==0)?0:((L2==1)?32:128);
  constexpr int AO  = (LO==0)?0:((LO==1)?1:4);

  for (int e = tid; e < K*D1*D2; e += NT) sC[e] = g_C[p][e];
  const float* wsp = ws + (size_t)p * 32768;

  for (int ch = ch0; ch < ch0 + CHPC; ++ch){
    __syncthreads();
    // prefetch weights into registers (hide L2 latency under T-build)
    float wreg[16];
    #pragma unroll
    for (int r = 0; r < 16; ++r)
      wreg[r] = __ldg(wsp + ch*2048 + r*128 + tid);

    // dense unrolled T-build: thread owns (c, zb); pass rp covers z = zb+4rp, zb+4rp+2
    {
      int c  = tid & 63;
      int zb = tid >> 6;            // 0 or 1
      int uv = ch*CHK + c;
      int u  = uv >> 5, v = uv & 31;
      #pragma unroll
      for (int rp = 0; rp < 2; ++rp){
        int za = zb + rp*4;
        int zc = za + 2;
        float A0[D1], A1[D1], B0[D2], B1[D2];
        #pragma unroll
        for (int i = 0; i < D1; ++i){
          A0[i] = x1s[za*X1S + O1 + u*D1 + i];
          A1[i] = x1s[zc*X1S + O1 + u*D1 + i];
        }
        #pragma unroll
        for (int j = 0; j < D2; ++j){
          B0[j] = x2t[za*X2S + O2T + j*32 + v];
          B1[j] = x2t[zc*X2S + O2T + j*32 + v];
        }
        float t0[K], t1[K];
        #pragma unroll
        for (int k = 0; k < K; ++k){ t0[k]=0.f; t1[k]=0.f; }
        #pragma unroll
        for (int i = 0; i < D1; ++i){
          #pragma unroll
          for (int j = 0; j < D2; ++j){
            float p0 = A0[i]*B0[j];
            float p1 = A1[i]*B1[j];
            #pragma unroll
            for (int k = 0; k < K; ++k){
              float cf = sC[(i*D2+j)*K + k];
              t0[k] = fmaf(cf, p0, t0[k]);
              t1[k] = fmaf(cf, p1, t1[k]);
            }
          }
        }
        int zp = rp*2 + zb;
        #pragma unroll
        for (int k = 0; k < K; ++k){
          unsigned long long pr; PK2(pr, t0[k], t1[k]);
          Tp[(zp*K + k)*TSTR2 + c] = pr;
        }
      }
    }
    // store weights NATURAL [c][w] layout: coalesced, conflict-free
    #pragma unroll
    for (int r = 0; r < 16; ++r)
      wss[r*128 + tid] = wreg[r];
    __syncthreads();
    // sweep: thread owns (w, z-pair zps); FFMA2 on u64 pair accumulators
    #pragma unroll 4
    for (int c2 = 0; c2 < CHK/2; ++c2){
      float wv0 = wss[(c2*2+0)*32 + w];
      float wv1 = wss[(c2*2+1)*32 + w];
      unsigned long long wp0, wp1;
      PK2(wp0, wv0, wv0); PK2(wp1, wv1, wv1);
      #pragma unroll
      for (int k = 0; k < K; ++k){
        ulonglong2 t = *(const ulonglong2*)(Tp + (zps*K + k)*TSTR2 + c2*2);
        FMA2(acc[AO+k], wp0, t.x);
        FMA2(acc[AO+k], wp1, t.y);
      }
    }
  }
}

__global__ void __launch_bounds__(NT, 5) tp_kernel(
    const float* __restrict__ x1, const float* __restrict__ x2,
    const float* __restrict__ ws)
{
  __shared__ float x1s[BZ*X1S];
  __shared__ float x2t[BZ*X2S];
  __shared__ float wss[64*32];
  __shared__ __align__(16) unsigned long long Tp[4*5*TSTR2];
  __shared__ float sC [125];

  int tid  = threadIdx.x;
  int w    = tid & 31;
  int zps  = tid >> 5;     // z-pair index 0..3
  int bid  = blockIdx.x;
  int half = bid & (UVS-1);
  int ch0  = half * CHPC;
  int zbase = (bid >> 3) * BZ;

  for (int e = tid; e < BZ*DIMF; e += NT){
    int z = e / DIMF, c = e - z*DIMF;
    x1s[z*X1S + c] = x1[(size_t)(zbase+z)*DIMF + c];
    float v2 = x2[(size_t)(zbase+z)*DIMF + c];
    int dst;
    if (c < 32) dst = c;
    else if (c < 128){ int idx = c - 32;  dst = 32  + (idx % 3)*32 + idx/3; }
    else             { int idx = c - 128; dst = 128 + (idx % 5)*32 + idx/5; }
    x2t[z*X2S + dst] = v2;
  }

  unsigned long long acc[9];
  #pragma unroll
  for (int i = 0; i < 9; ++i) acc[i] = 0ull;

  process_path<0,0,0>( 0, ch0, ws, x1s,x2t, wss,Tp,sC, acc, tid,w,zps);
  process_path<1,1,0>( 1, ch0, ws, x1s,x2t, wss,Tp,sC, acc, tid,w,zps);
  process_path<2,2,0>( 2, ch0, ws, x1s,x2t, wss,Tp,sC, acc, tid,w,zps);
  process_path<0,1,1>( 3, ch0, ws, x1s,x2t, wss,Tp,sC, acc, tid,w,zps);
  process_path<1,0,1>( 4, ch0, ws, x1s,x2t, wss,Tp,sC, acc, tid,w,zps);
  process_path<1,2,1>( 5, ch0, ws, x1s,x2t, wss,Tp,sC, acc, tid,w,zps);
  process_path<2,1,1>( 6, ch0, ws, x1s,x2t, wss,Tp,sC, acc, tid,w,zps);
  process_path<0,2,2>( 7, ch0, ws, x1s,x2t, wss,Tp,sC, acc, tid,w,zps);
  process_path<1,1,2>( 8, ch0, ws, x1s,x2t, wss,Tp,sC, acc, tid,w,zps);
  process_path<2,0,2>( 9, ch0, ws, x1s,x2t, wss,Tp,sC, acc, tid,w,zps);
  process_path<2,2,2>(10, ch0, ws, x1s,x2t, wss,Tp,sC, acc, tid,w,zps);

  const float A0f = 0.01804219591217583f;   // sqrt(1/3072)
  const float A1f = 0.02706329386826371f;   // sqrt(3)/64
  const float A2f = 0.03493856214843422f;   // sqrt(5)/64

  // pair (z, z+2) with z = (zps>>1)*4 + (zps&1)
  int zq = (zps >> 1)*4 + (zps & 1);
  float* o0 = g_part[half] + (size_t)(zbase + zq) * DIMF;
  float* o1 = g_part[half] + (size_t)(zbase + zq + 2) * DIMF;
  float lo, hi;
  UPK2(lo, hi, acc[0]);
  o0[w] = A0f * lo;  o1[w] = A0f * hi;
  #pragma unroll
  for (int k = 0; k < 3; ++k){
    UPK2(lo, hi, acc[1+k]);
    o0[32 + w*3 + k] = A1f * lo;
    o1[32 + w*3 + k] = A1f * hi;
  }
  #pragma unroll
  for (int k = 0; k < 5; ++k){
    UPK2(lo, hi, acc[4+k]);
    o0[128 + w*5 + k] = A2f * lo;
    o1[128 + w*5 + k] = A2f * hi;
  }
}

__global__ void reduce_kernel(float* __restrict__ out){
  int i = blockIdx.x * blockDim.x + threadIdx.x;
  float4 r = make_float4(0.f, 0.f, 0.f, 0.f);
  #pragma unroll
  for (int s = 0; s < UVS; ++s){
    float4 a = ((const float4*)g_part[s])[i];
    r.x += a.x; r.y += a.y; r.z += a.z; r.w += a.w;
  }
  ((float4*)out)[i] = r;
}

extern "C" void kernel_launch(void* const* d_in, const int* in_sizes, int n_in,
                              void* d_out, int out_size) {
  const float* x1 = (const float*)d_in[0];
  const float* x2 = (const float*)d_in[1];
  const float* ws = (const float*)d_in[2];
  float* out = (float*)d_out;
  (void)in_sizes; (void)n_in; (void)out_size;

  static float h_C[NPATH][125];
  compute_w3j_dense(h_C);
  cudaMemcpyToSymbolAsync(g_C, h_C, sizeof(h_C), 0, cudaMemcpyHostToDevice, 0);

  tp_kernel<<<(2048/BZ)*UVS, NT>>>(x1, x2, ws);
  reduce_kernel<<<(2048*DIMF/4)/256, 256>>>(out);
}

// round 13
// speedup vs baseline: 1.2993x; 1.2993x over previous
#include <cuda_runtime.h>
#include <cuda_bf16.h>
#include <math.h>
#include <string.h>

#define NPATH 11
#define DIMF  288
#define ZT    32
#define UVS   4
#define NT    256

static const int hc_l1[NPATH] = {0,1,2,0,1,1,2,0,1,2,2};
static const int hc_l2[NPATH] = {0,1,2,1,0,2,1,2,1,0,2};
static const int hc_lo[NPATH] = {0,0,0,1,1,1,1,2,2,2,2};

__device__ float g_C[NPATH][125];
__device__ float g_part[UVS][2048*DIMF];

// ---------------- host-side Wigner-3j (exact port of reference) ------------
static double hfact(int n){ double r=1.0; for(int i=2;i<=n;++i) r*=i; return r; }

static double h_su2(int j1,int m1,int j2,int m2,int j3,int m3){
  if (m1+m2 != m3) return 0.0;
  int vmin = -j1+j2+m3; if (-j1+m1 > vmin) vmin = -j1+m1; if (vmin < 0) vmin = 0;
  int vmax = j2+j3+m1; if (j3-j1+j2 < vmax) vmax = j3-j1+j2; if (j3+m3 < vmax) vmax = j3+m3;
  if (vmax < vmin) return 0.0;
  double C = sqrt((2.0*j3+1.0)
    * hfact(j3+j1-j2)*hfact(j3-j1+j2)*hfact(j1+j2-j3)*hfact(j3+m3)*hfact(j3-m3)
    / (hfact(j1+j2+j3+1)*hfact(j1-m1)*hfact(j1+m1)*hfact(j2-m2)*hfact(j2+m2)));
  double S = 0.0;
  for (int v = vmin; v <= vmax; ++v){
    double t = hfact(j2+j3+m1-v)*hfact(j1-m1+v)
             / (hfact(v)*hfact(j3-j1+j2-v)*hfact(j3+m3-v)*hfact(v+j1-j2-m3));
    S += ((v+j2+m2)&1) ? -t : t;
  }
  return C*S;
}

static void h_q(int l,int a,int b,double&re,double&im){
  double r=0.0,i=0.0; int m=a-l; const double s2=0.70710678118654752440;
  if (m<0){ if (b==l-m) r=s2; if (b==l+m) i=-s2; }
  else if (m==0){ if (b==l) r=1.0; }
  else { double s=(m&1)?-1.0:1.0; if (b==l+m) r=s*s2; if (b==l-m) i=s*s2; }
  if (l==1){ double t=r; r=i; i=-t; }
  else if (l==2){ r=-r; i=-i; }
  re=r; im=i;
}

static void compute_w3j_dense(float Cd[NPATH][125]){
  for (int p=0;p<NPATH;++p){
    int l1=hc_l1[p], l2=hc_l2[p], l3=hc_lo[p];
    int d1=2*l1+1, d2=2*l2+1, d3=2*l3+1;
    double cg[125]; for (int e=0;e<125;++e) cg[e]=0.0;
    for (int i=0;i<d1;++i) for (int k=0;k<d2;++k){
      int m1=i-l1, m2=k-l2;
      if (m1+m2 >= -l3 && m1+m2 <= l3)
        cg[(i*d2+k)*d3 + (l3+m1+m2)] = h_su2(l1,m1,l2,m2,l3,m1+m2);
    }
    double Cv[125]; double nrm=0.0;
    for (int jj=0;jj<d1;++jj) for (int ll=0;ll<d2;++ll) for (int mm=0;mm<d3;++mm){
      double cr=0.0;
      for (int i=0;i<d1;++i){
        double q1r,q1i; h_q(l1,i,jj,q1r,q1i);
        if (q1r==0.0 && q1i==0.0) continue;
        for (int k=0;k<d2;++k){
          double q2r,q2i; h_q(l2,k,ll,q2r,q2i);
          if (q2r==0.0 && q2i==0.0) continue;
          int n=(i-l1)+(k-l2)+l3;
          if (n<0 || n>=d3) continue;
          double g=cg[(i*d2+k)*d3+n];
          if (g==0.0) continue;
          double q3r,q3i; h_q(l3,n,mm,q3r,q3i); q3i=-q3i;
          double ar=q1r*q2r-q1i*q2i, ai=q1r*q2i+q1i*q2r;
          cr += g*(ar*q3r - ai*q3i);
        }
      }
      Cv[(jj*d2+ll)*d3+mm]=cr; nrm += cr*cr;
    }
    double inorm = 1.0/sqrt(nrm);
    for (int e=0;e<125;++e) Cd[p][e]=0.f;
    for (int e=0;e<d1*d2*d3;++e) Cd[p][e] = (float)(Cv[e]*inorm);
  }
}

// ---------------- device helpers -------------------------------------------
__device__ __forceinline__ unsigned smem_u32(const void* p){
  unsigned a;
  asm("{ .reg .u64 t; cvta.to.shared.u64 t, %1; cvt.u32.u64 %0, t; }" : "=r"(a) : "l"(p));
  return a;
}
__device__ __forceinline__ void ldsm4(unsigned* r, unsigned addr){
  asm volatile("ldmatrix.sync.aligned.m8n8.x4.shared.b16 {%0,%1,%2,%3}, [%4];"
    : "=r"(r[0]),"=r"(r[1]),"=r"(r[2]),"=r"(r[3]) : "r"(addr));
}
__device__ __forceinline__ void ldsm2t(unsigned* r, unsigned addr){
  asm volatile("ldmatrix.sync.aligned.m8n8.x2.trans.shared.b16 {%0,%1}, [%2];"
    : "=r"(r[0]),"=r"(r[1]) : "r"(addr));
}
__device__ __forceinline__ void mma_bf16(float* d, const unsigned* a, const unsigned* b){
  asm volatile("mma.sync.aligned.m16n8k16.row.col.f32.bf16.bf16.f32 "
    "{%0,%1,%2,%3}, {%4,%5,%6,%7}, {%8,%9}, {%0,%1,%2,%3};"
    : "+f"(d[0]),"+f"(d[1]),"+f"(d[2]),"+f"(d[3])
    : "r"(a[0]),"r"(a[1]),"r"(a[2]),"r"(a[3]), "r"(b[0]),"r"(b[1]));
}
__device__ __forceinline__ unsigned split_pack(float t){
  __nv_bfloat16 h = __float2bfloat16(t);
  float res = t - __bfloat162float(h);
  __nv_bfloat16 l = __float2bfloat16(res);
  return (unsigned)__bfloat16_as_ushort(h) | ((unsigned)__bfloat16_as_ushort(l) << 16);
}

#define ASTR 144   // A tile row stride bytes (72 bf16): LDSM bank step 4, conflict-free
#define ATSZ (32*ASTR)
#define BSTR 80    // B tile row stride bytes (40 bf16): LDSM bank step 20, conflict-free

// ---------------- per-path build + MMA --------------------------------------
template<int L1, int L2, int LO, int CB>
__device__ __forceinline__ void do_path(
    int p,
    const float* __restrict__ x1, const float* __restrict__ x2,
    const float* __restrict__ ws,
    float acc[9][4], const float* sC,
    unsigned char* sA, unsigned char* sB1, unsigned char* sB2,
    unsigned aA, unsigned aB1, unsigned aB2,
    int zbase, int uvh, int tid, int lane, int zh, int nt)
{
  constexpr int D1 = 2*L1+1, D2 = 2*L2+1, K = 2*LO+1;
  constexpr int O1 = (L1==0)?0:((L1==1)?32:128);
  constexpr int O2 = (L2==0)?0:((L2==1)?32:128);
  const float* Cp = sC + p*125;

  #pragma unroll 1
  for (int ch = 0; ch < 8; ++ch){
    int u = uvh*8 + ch;
    // ---- stage weights: B1 rows (2v,2v+1)=(Wh,Wh), B2=(Wl,0)
    #pragma unroll
    for (int r = 0; r < 4; ++r){
      int idx = r*NT + tid;
      int v = idx >> 5, w = idx & 31;
      float val = __ldg(ws + (size_t)p*32768 + (size_t)(u*32+v)*32 + w);
      __nv_bfloat16 h = __float2bfloat16(val);
      float res = val - __bfloat162float(h);
      __nv_bfloat16 l = __float2bfloat16(res);
      unsigned short hb = __bfloat16_as_ushort(h);
      unsigned short lb = __bfloat16_as_ushort(l);
      *(unsigned short*)(sB1 + (2*v  )*BSTR + w*2) = hb;
      *(unsigned short*)(sB1 + (2*v+1)*BSTR + w*2) = hb;
      *(unsigned short*)(sB2 + (2*v  )*BSTR + w*2) = lb;
      *(unsigned short*)(sB2 + (2*v+1)*BSTR + w*2) = 0;
    }
    // ---- build T (scalar fp32), split to bf16 pairs into A_k tiles
    {
      int z  = tid >> 3;
      int vb = tid & 7;
      float a1[D1];
      const float* a1p = x1 + (size_t)(zbase + z)*DIMF + O1 + u*D1;
      #pragma unroll
      for (int i = 0; i < D1; ++i) a1[i] = __ldg(a1p + i);
      const float* x2p = x2 + (size_t)(zbase + z)*DIMF + O2;
      #pragma unroll
      for (int vi = 0; vi < 4; ++vi){
        int v = vb*4 + vi;
        float b[D2];
        #pragma unroll
        for (int j = 0; j < D2; ++j) b[j] = __ldg(x2p + v*D2 + j);
        float t[K];
        #pragma unroll
        for (int k = 0; k < K; ++k) t[k] = 0.f;
        #pragma unroll
        for (int i = 0; i < D1; ++i){
          #pragma unroll
          for (int j = 0; j < D2; ++j){
            float pr = a1[i]*b[j];
            #pragma unroll
            for (int k = 0; k < K; ++k)
              t[k] = fmaf(Cp[(i*D2+j)*K + k], pr, t[k]);
          }
        }
        #pragma unroll
        for (int k = 0; k < K; ++k)
          *(unsigned*)(sA + k*ATSZ + z*ASTR + v*4) = split_pack(t[k]);
      }
    }
    __syncthreads();
    // ---- warp MMAs: warp owns (z-half zh, n8-tile nt), all K chains
    #pragma unroll
    for (int kb = 0; kb < 4; ++kb){
      unsigned bf1[2], bf2[2];
      unsigned brow = (unsigned)((kb*16 + (lane & 15))*BSTR + nt*16);
      ldsm2t(bf1, aB1 + brow);
      ldsm2t(bf2, aB2 + brow);
      #pragma unroll
      for (int k = 0; k < K; ++k){
        unsigned af[4];
        ldsm4(af, aA + (unsigned)(k*ATSZ + (zh*16 + (lane & 15))*ASTR
                                  + kb*32 + (lane >> 4)*16));
        mma_bf16(acc[CB + k], af, bf1);
        mma_bf16(acc[CB + k], af, bf2);
      }
    }
    __syncthreads();
  }
}

// ---------------- main kernel ----------------------------------------------
__global__ void __launch_bounds__(NT, 2) tp_mma_kernel(
    const float* __restrict__ x1, const float* __restrict__ x2,
    const float* __restrict__ ws)
{
  __shared__ __align__(16) unsigned char sA[5*ATSZ];     // 23040 B
  __shared__ __align__(16) unsigned char sB1[64*BSTR];   // 5120 B
  __shared__ __align__(16) unsigned char sB2[64*BSTR];   // 5120 B
  __shared__ float sC[NPATH*125];

  const int tid  = threadIdx.x;
  const int lane = tid & 31;
  const int wid  = tid >> 5;
  const int zh   = wid >> 2;      // z-half: 0/1
  const int nt   = wid & 3;       // n8 tile: 0..3
  const int bid  = blockIdx.x;
  const int uvh  = bid & (UVS-1);
  const int zbase = (bid >> 2) * ZT;

  for (int e = tid; e < NPATH*125; e += NT)
    sC[e] = g_C[e/125][e%125];
  __syncthreads();

  unsigned aA  = smem_u32(sA);
  unsigned aB1 = smem_u32(sB1);
  unsigned aB2 = smem_u32(sB2);

  float acc[9][4];
  #pragma unroll
  for (int c = 0; c < 9; ++c)
    #pragma unroll
    for (int r = 0; r < 4; ++r) acc[c][r] = 0.f;

  do_path<0,0,0,0>( 0, x1,x2,ws, acc,sC, sA,sB1,sB2, aA,aB1,aB2, zbase,uvh,tid,lane,zh,nt);
  do_path<1,1,0,0>( 1, x1,x2,ws, acc,sC, sA,sB1,sB2, aA,aB1,aB2, zbase,uvh,tid,lane,zh,nt);
  do_path<2,2,0,0>( 2, x1,x2,ws, acc,sC, sA,sB1,sB2, aA,aB1,aB2, zbase,uvh,tid,lane,zh,nt);
  do_path<0,1,1,1>( 3, x1,x2,ws, acc,sC, sA,sB1,sB2, aA,aB1,aB2, zbase,uvh,tid,lane,zh,nt);
  do_path<1,0,1,1>( 4, x1,x2,ws, acc,sC, sA,sB1,sB2, aA,aB1,aB2, zbase,uvh,tid,lane,zh,nt);
  do_path<1,2,1,1>( 5, x1,x2,ws, acc,sC, sA,sB1,sB2, aA,aB1,aB2, zbase,uvh,tid,lane,zh,nt);
  do_path<2,1,1,1>( 6, x1,x2,ws, acc,sC, sA,sB1,sB2, aA,aB1,aB2, zbase,uvh,tid,lane,zh,nt);
  do_path<0,2,2,4>( 7, x1,x2,ws, acc,sC, sA,sB1,sB2, aA,aB1,aB2, zbase,uvh,tid,lane,zh,nt);
  do_path<1,1,2,4>( 8, x1,x2,ws, acc,sC, sA,sB1,sB2, aA,aB1,aB2, zbase,uvh,tid,lane,zh,nt);
  do_path<2,0,2,4>( 9, x1,x2,ws, acc,sC, sA,sB1,sB2, aA,aB1,aB2, zbase,uvh,tid,lane,zh,nt);
  do_path<2,2,2,4>(10, x1,x2,ws, acc,sC, sA,sB1,sB2, aA,aB1,aB2, zbase,uvh,tid,lane,zh,nt);

  const float A0f = 0.01804219591217583f;   // sqrt(1/3072)
  const float A1f = 0.02706329386826371f;   // sqrt(3)/64
  const float A2f = 0.03493856214843422f;   // sqrt(5)/64

  // D frag layout: d0=(r,c) d1=(r,c+1) d2=(r+8,c) d3=(r+8,c+1); r=lane>>2, c=(lane&3)*2
  int r0 = zh*16 + (lane >> 2);
  int c0 = nt*8 + (lane & 3)*2;
  float* b0 = g_part[uvh] + (size_t)(zbase + r0)     * DIMF;
  float* b1 = g_part[uvh] + (size_t)(zbase + r0 + 8) * DIMF;

  b0[c0]   = A0f*acc[0][0];  b0[c0+1] = A0f*acc[0][1];
  b1[c0]   = A0f*acc[0][2];  b1[c0+1] = A0f*acc[0][3];
  #pragma unroll
  for (int c = 0; c < 3; ++c){
    b0[32 + c0*3 + c]     = A1f*acc[1+c][0];
    b0[32 + (c0+1)*3 + c] = A1f*acc[1+c][1];
    b1[32 + c0*3 + c]     = A1f*acc[1+c][2];
    b1[32 + (c0+1)*3 + c] = A1f*acc[1+c][3];
  }
  #pragma unroll
  for (int c = 0; c < 5; ++c){
    b0[128 + c0*5 + c]     = A2f*acc[4+c][0];
    b0[128 + (c0+1)*5 + c] = A2f*acc[4+c][1];
    b1[128 + c0*5 + c]     = A2f*acc[4+c][2];
    b1[128 + (c0+1)*5 + c] = A2f*acc[4+c][3];
  }
}

__global__ void reduce_kernel(float* __restrict__ out){
  int i = blockIdx.x * blockDim.x + threadIdx.x;
  float4 r = make_float4(0.f, 0.f, 0.f, 0.f);
  #pragma unroll
  for (int s = 0; s < UVS; ++s){
    float4 a = ((const float4*)g_part[s])[i];
    r.x += a.x; r.y += a.y; r.z += a.z; r.w += a.w;
  }
  ((float4*)out)[i] = r;
}

extern "C" void kernel_launch(void* const* d_in, const int* in_sizes, int n_in,
                              void* d_out, int out_size) {
  const float* x1 = (const float*)d_in[0];
  const float* x2 = (const float*)d_in[1];
  const float* ws = (const float*)d_in[2];
  float* out = (float*)d_out;
  (void)in_sizes; (void)n_in; (void)out_size;

  static float h_C[NPATH][125];
  compute_w3j_dense(h_C);
  cudaMemcpyToSymbolAsync(g_C, h_C, sizeof(h_C), 0, cudaMemcpyHostToDevice, 0);

  tp_mma_kernel<<<(2048/ZT)*UVS, NT>>>(x1, x2, ws);
  reduce_kernel<<<(2048*DIMF/4)/256, 256>>>(out);
}

// round 14
// speedup vs baseline: 1.8049x; 1.3892x over previous
#include <cuda_runtime.h>
#include <cuda_bf16.h>
#include <math.h>
#include <string.h>

#define NPATH 11
#define DIMF  288
#define ZT    32
#define UVS   4
#define NT    256

static const int hc_l1[NPATH] = {0,1,2,0,1,1,2,0,1,2,2};
static const int hc_l2[NPATH] = {0,1,2,1,0,2,1,2,1,0,2};
static const int hc_lo[NPATH] = {0,0,0,1,1,1,1,2,2,2,2};

__device__ float g_C[NPATH][125];
__device__ float g_part[UVS][2048*DIMF];

// ---------------- host-side Wigner-3j (exact port of reference) ------------
static double hfact(int n){ double r=1.0; for(int i=2;i<=n;++i) r*=i; return r; }

static double h_su2(int j1,int m1,int j2,int m2,int j3,int m3){
  if (m1+m2 != m3) return 0.0;
  int vmin = -j1+j2+m3; if (-j1+m1 > vmin) vmin = -j1+m1; if (vmin < 0) vmin = 0;
  int vmax = j2+j3+m1; if (j3-j1+j2 < vmax) vmax = j3-j1+j2; if (j3+m3 < vmax) vmax = j3+m3;
  if (vmax < vmin) return 0.0;
  double C = sqrt((2.0*j3+1.0)
    * hfact(j3+j1-j2)*hfact(j3-j1+j2)*hfact(j1+j2-j3)*hfact(j3+m3)*hfact(j3-m3)
    / (hfact(j1+j2+j3+1)*hfact(j1-m1)*hfact(j1+m1)*hfact(j2-m2)*hfact(j2+m2)));
  double S = 0.0;
  for (int v = vmin; v <= vmax; ++v){
    double t = hfact(j2+j3+m1-v)*hfact(j1-m1+v)
             / (hfact(v)*hfact(j3-j1+j2-v)*hfact(j3+m3-v)*hfact(v+j1-j2-m3));
    S += ((v+j2+m2)&1) ? -t : t;
  }
  return C*S;
}

static void h_q(int l,int a,int b,double&re,double&im){
  double r=0.0,i=0.0; int m=a-l; const double s2=0.70710678118654752440;
  if (m<0){ if (b==l-m) r=s2; if (b==l+m) i=-s2; }
  else if (m==0){ if (b==l) r=1.0; }
  else { double s=(m&1)?-1.0:1.0; if (b==l+m) r=s*s2; if (b==l-m) i=s*s2; }
  if (l==1){ double t=r; r=i; i=-t; }
  else if (l==2){ r=-r; i=-i; }
  re=r; im=i;
}

static void compute_w3j_dense(float Cd[NPATH][125]){
  for (int p=0;p<NPATH;++p){
    int l1=hc_l1[p], l2=hc_l2[p], l3=hc_lo[p];
    int d1=2*l1+1, d2=2*l2+1, d3=2*l3+1;
    double cg[125]; for (int e=0;e<125;++e) cg[e]=0.0;
    for (int i=0;i<d1;++i) for (int k=0;k<d2;++k){
      int m1=i-l1, m2=k-l2;
      if (m1+m2 >= -l3 && m1+m2 <= l3)
        cg[(i*d2+k)*d3 + (l3+m1+m2)] = h_su2(l1,m1,l2,m2,l3,m1+m2);
    }
    double Cv[125]; double nrm=0.0;
    for (int jj=0;jj<d1;++jj) for (int ll=0;ll<d2;++ll) for (int mm=0;mm<d3;++mm){
      double cr=0.0;
      for (int i=0;i<d1;++i){
        double q1r,q1i; h_q(l1,i,jj,q1r,q1i);
        if (q1r==0.0 && q1i==0.0) continue;
        for (int k=0;k<d2;++k){
          double q2r,q2i; h_q(l2,k,ll,q2r,q2i);
          if (q2r==0.0 && q2i==0.0) continue;
          int n=(i-l1)+(k-l2)+l3;
          if (n<0 || n>=d3) continue;
          double g=cg[(i*d2+k)*d3+n];
          if (g==0.0) continue;
          double q3r,q3i; h_q(l3,n,mm,q3r,q3i); q3i=-q3i;
          double ar=q1r*q2r-q1i*q2i, ai=q1r*q2i+q1i*q2r;
          cr += g*(ar*q3r - ai*q3i);
        }
      }
      Cv[(jj*d2+ll)*d3+mm]=cr; nrm += cr*cr;
    }
    double inorm = 1.0/sqrt(nrm);
    for (int e=0;e<125;++e) Cd[p][e]=0.f;
    for (int e=0;e<d1*d2*d3;++e) Cd[p][e] = (float)(Cv[e]*inorm);
  }
}

// ---------------- device helpers -------------------------------------------
__device__ __forceinline__ unsigned smem_u32(const void* p){
  unsigned a;
  asm("{ .reg .u64 t; cvta.to.shared.u64 t, %1; cvt.u32.u64 %0, t; }" : "=r"(a) : "l"(p));
  return a;
}
__device__ __forceinline__ void ldsm4(unsigned* r, unsigned addr){
  asm volatile("ldmatrix.sync.aligned.m8n8.x4.shared.b16 {%0,%1,%2,%3}, [%4];"
    : "=r"(r[0]),"=r"(r[1]),"=r"(r[2]),"=r"(r[3]) : "r"(addr));
}
__device__ __forceinline__ void ldsm2t(unsigned* r, unsigned addr){
  asm volatile("ldmatrix.sync.aligned.m8n8.x2.trans.shared.b16 {%0,%1}, [%2];"
    : "=r"(r[0]),"=r"(r[1]) : "r"(addr));
}
__device__ __forceinline__ void mma_bf16(float* d, const unsigned* a, const unsigned* b){
  asm volatile("mma.sync.aligned.m16n8k16.row.col.f32.bf16.bf16.f32 "
    "{%0,%1,%2,%3}, {%4,%5,%6,%7}, {%8,%9}, {%0,%1,%2,%3};"
    : "+f"(d[0]),"+f"(d[1]),"+f"(d[2]),"+f"(d[3])
    : "r"(a[0]),"r"(a[1]),"r"(a[2]),"r"(a[3]), "r"(b[0]),"r"(b[1]));
}
// pack (hi=bf16(t)) in low 16, (lo=bf16(t-hi)) in high 16
__device__ __forceinline__ unsigned split_pack(float t){
  __nv_bfloat16 h = __float2bfloat16(t);
  float hf = __bfloat162float(h);
  float res = t - hf;
  unsigned r;
  asm("cvt.rn.bf16x2.f32 %0, %1, %2;" : "=r"(r) : "f"(res), "f"(hf));
  return r;
}

#define ASTR 144   // A tile row stride bytes (72 bf16): LDSM bank step 4, conflict-free
#define ATSZ (32*ASTR)
#define BSTR 80    // B tile row stride bytes (40 bf16): LDSM bank step 20, conflict-free

// ---------------- per-path build + MMA --------------------------------------
template<int L1, int L2, int LO, int CB>
__device__ __forceinline__ void do_path(
    int p,
    const float* __restrict__ x1, const float* __restrict__ x2,
    const float* __restrict__ ws,
    float acc[9][4], const float* sC,
    unsigned char* sA, unsigned char* sB1, unsigned char* sB2,
    unsigned aA, unsigned aB1, unsigned aB2,
    int zbase, int uvh, int tid, int lane, int zh, int nt)
{
  constexpr int D1 = 2*L1+1, D2 = 2*L2+1, K = 2*LO+1;
  constexpr int O1 = (L1==0)?0:((L1==1)?32:128);
  constexpr int O2 = (L2==0)?0:((L2==1)?32:128);
  const float* Cp = sC + p*125;

  const int z  = tid >> 3;
  const int vb = tid & 7;
  // hoist x2 loads: u-independent, reused across all 8 chunks
  float b[4][D2];
  {
    const float* x2p = x2 + (size_t)(zbase + z)*DIMF + O2;
    #pragma unroll
    for (int vi = 0; vi < 4; ++vi)
      #pragma unroll
      for (int j = 0; j < D2; ++j)
        b[vi][j] = __ldg(x2p + (vb*4 + vi)*D2 + j);
  }

  #pragma unroll 1
  for (int ch = 0; ch < 8; ++ch){
    int u = uvh*8 + ch;
    // ---- stage weights: B1 rows (2v,2v+1)=(Wh,Wh), B2=(Wl,0)
    #pragma unroll
    for (int r = 0; r < 4; ++r){
      int idx = r*NT + tid;
      int v = idx >> 5, w = idx & 31;
      float val = __ldg(ws + (size_t)p*32768 + (size_t)(u*32+v)*32 + w);
      __nv_bfloat16 h = __float2bfloat16(val);
      float res = val - __bfloat162float(h);
      __nv_bfloat16 l = __float2bfloat16(res);
      unsigned short hb = __bfloat16_as_ushort(h);
      unsigned short lb = __bfloat16_as_ushort(l);
      *(unsigned short*)(sB1 + (2*v  )*BSTR + w*2) = hb;
      *(unsigned short*)(sB1 + (2*v+1)*BSTR + w*2) = hb;
      *(unsigned short*)(sB2 + (2*v  )*BSTR + w*2) = lb;
      *(unsigned short*)(sB2 + (2*v+1)*BSTR + w*2) = 0;
    }
    // ---- build T via G-factorization: G[k][j] = sum_i C[i,j,k]*x1[i]
    {
      float a1[D1];
      const float* a1p = x1 + (size_t)(zbase + z)*DIMF + O1 + u*D1;
      #pragma unroll
      for (int i = 0; i < D1; ++i) a1[i] = __ldg(a1p + i);
      float G[K][D2];
      #pragma unroll
      for (int k = 0; k < K; ++k)
        #pragma unroll
        for (int j = 0; j < D2; ++j){
          float g = 0.f;
          #pragma unroll
          for (int i = 0; i < D1; ++i)
            g = fmaf(Cp[(i*D2+j)*K + k], a1[i], g);
          G[k][j] = g;
        }
      #pragma unroll
      for (int vi = 0; vi < 4; ++vi){
        int v = vb*4 + vi;
        float t[K];
        #pragma unroll
        for (int k = 0; k < K; ++k){
          float s = 0.f;
          #pragma unroll
          for (int j = 0; j < D2; ++j)
            s = fmaf(G[k][j], b[vi][j], s);
          t[k] = s;
        }
        #pragma unroll
        for (int k = 0; k < K; ++k)
          *(unsigned*)(sA + k*ATSZ + z*ASTR + v*4) = split_pack(t[k]);
      }
    }
    __syncthreads();
    // ---- warp MMAs: warp owns (z-half zh, n8-tile nt), all K chains
    #pragma unroll
    for (int kb = 0; kb < 4; ++kb){
      unsigned bf1[2], bf2[2];
      unsigned brow = (unsigned)((kb*16 + (lane & 15))*BSTR + nt*16);
      ldsm2t(bf1, aB1 + brow);
      ldsm2t(bf2, aB2 + brow);
      #pragma unroll
      for (int k = 0; k < K; ++k){
        unsigned af[4];
        ldsm4(af, aA + (unsigned)(k*ATSZ + (zh*16 + (lane & 15))*ASTR
                                  + kb*32 + (lane >> 4)*16));
        mma_bf16(acc[CB + k], af, bf1);
        mma_bf16(acc[CB + k], af, bf2);
      }
    }
    __syncthreads();
  }
}

// ---------------- main kernel ----------------------------------------------
__global__ void __launch_bounds__(NT, 2) tp_mma_kernel(
    const float* __restrict__ x1, const float* __restrict__ x2,
    const float* __restrict__ ws)
{
  __shared__ __align__(16) unsigned char sA[5*ATSZ];     // 23040 B
  __shared__ __align__(16) unsigned char sB1[64*BSTR];   // 5120 B
  __shared__ __align__(16) unsigned char sB2[64*BSTR];   // 5120 B
  __shared__ float sC[NPATH*125];

  const int tid  = threadIdx.x;
  const int lane = tid & 31;
  const int wid  = tid >> 5;
  const int zh   = wid >> 2;      // z-half: 0/1
  const int nt   = wid & 3;       // n8 tile: 0..3
  const int bid  = blockIdx.x;
  const int uvh  = bid & (UVS-1);
  const int zbase = (bid >> 2) * ZT;

  for (int e = tid; e < NPATH*125; e += NT)
    sC[e] = g_C[e/125][e%125];
  __syncthreads();

  unsigned aA  = smem_u32(sA);
  unsigned aB1 = smem_u32(sB1);
  unsigned aB2 = smem_u32(sB2);

  float acc[9][4];
  #pragma unroll
  for (int c = 0; c < 9; ++c)
    #pragma unroll
    for (int r = 0; r < 4; ++r) acc[c][r] = 0.f;

  do_path<0,0,0,0>( 0, x1,x2,ws, acc,sC, sA,sB1,sB2, aA,aB1,aB2, zbase,uvh,tid,lane,zh,nt);
  do_path<1,1,0,0>( 1, x1,x2,ws, acc,sC, sA,sB1,sB2, aA,aB1,aB2, zbase,uvh,tid,lane,zh,nt);
  do_path<2,2,0,0>( 2, x1,x2,ws, acc,sC, sA,sB1,sB2, aA,aB1,aB2, zbase,uvh,tid,lane,zh,nt);
  do_path<0,1,1,1>( 3, x1,x2,ws, acc,sC, sA,sB1,sB2, aA,aB1,aB2, zbase,uvh,tid,lane,zh,nt);
  do_path<1,0,1,1>( 4, x1,x2,ws, acc,sC, sA,sB1,sB2, aA,aB1,aB2, zbase,uvh,tid,lane,zh,nt);
  do_path<1,2,1,1>( 5, x1,x2,ws, acc,sC, sA,sB1,sB2, aA,aB1,aB2, zbase,uvh,tid,lane,zh,nt);
  do_path<2,1,1,1>( 6, x1,x2,ws, acc,sC, sA,sB1,sB2, aA,aB1,aB2, zbase,uvh,tid,lane,zh,nt);
  do_path<0,2,2,4>( 7, x1,x2,ws, acc,sC, sA,sB1,sB2, aA,aB1,aB2, zbase,uvh,tid,lane,zh,nt);
  do_path<1,1,2,4>( 8, x1,x2,ws, acc,sC, sA,sB1,sB2, aA,aB1,aB2, zbase,uvh,tid,lane,zh,nt);
  do_path<2,0,2,4>( 9, x1,x2,ws, acc,sC, sA,sB1,sB2, aA,aB1,aB2, zbase,uvh,tid,lane,zh,nt);
  do_path<2,2,2,4>(10, x1,x2,ws, acc,sC, sA,sB1,sB2, aA,aB1,aB2, zbase,uvh,tid,lane,zh,nt);

  const float A0f = 0.01804219591217583f;   // sqrt(1/3072)
  const float A1f = 0.02706329386826371f;   // sqrt(3)/64
  const float A2f = 0.03493856214843422f;   // sqrt(5)/64

  // D frag layout: d0=(r,c) d1=(r,c+1) d2=(r+8,c) d3=(r+8,c+1); r=lane>>2, c=(lane&3)*2
  int r0 = zh*16 + (lane >> 2);
  int c0 = nt*8 + (lane & 3)*2;
  float* b0 = g_part[uvh] + (size_t)(zbase + r0)     * DIMF;
  float* b1 = g_part[uvh] + (size_t)(zbase + r0 + 8) * DIMF;

  b0[c0]   = A0f*acc[0][0];  b0[c0+1] = A0f*acc[0][1];
  b1[c0]   = A0f*acc[0][2];  b1[c0+1] = A0f*acc[0][3];
  #pragma unroll
  for (int c = 0; c < 3; ++c){
    b0[32 + c0*3 + c]     = A1f*acc[1+c][0];
    b0[32 + (c0+1)*3 + c] = A1f*acc[1+c][1];
    b1[32 + c0*3 + c]     = A1f*acc[1+c][2];
    b1[32 + (c0+1)*3 + c] = A1f*acc[1+c][3];
  }
  #pragma unroll
  for (int c = 0; c < 5; ++c){
    b0[128 + c0*5 + c]     = A2f*acc[4+c][0];
    b0[128 + (c0+1)*5 + c] = A2f*acc[4+c][1];
    b1[128 + c0*5 + c]     = A2f*acc[4+c][2];
    b1[128 + (c0+1)*5 + c] = A2f*acc[4+c][3];
  }
}

__global__ void reduce_kernel(float* __restrict__ out){
  int i = blockIdx.x * blockDim.x + threadIdx.x;
  float4 r = make_float4(0.f, 0.f, 0.f, 0.f);
  #pragma unroll
  for (int s = 0; s < UVS; ++s){
    float4 a = ((const float4*)g_part[s])[i];
    r.x += a.x; r.y += a.y; r.z += a.z; r.w += a.w;
  }
  ((float4*)out)[i] = r;
}

extern "C" void kernel_launch(void* const* d_in, const int* in_sizes, int n_in,
                              void* d_out, int out_size) {
  const float* x1 = (const float*)d_in[0];
  const float* x2 = (const float*)d_in[1];
  const float* ws = (const float*)d_in[2];
  float* out = (float*)d_out;
  (void)in_sizes; (void)n_in; (void)out_size;

  static float h_C[NPATH][125];
  compute_w3j_dense(h_C);
  cudaMemcpyToSymbolAsync(g_C, h_C, sizeof(h_C), 0, cudaMemcpyHostToDevice, 0);

  tp_mma_kernel<<<(2048/ZT)*UVS, NT>>>(x1, x2, ws);
  reduce_kernel<<<(2048*DIMF/4)/256, 256>>>(out);
}

// round 15
// speedup vs baseline: 1.8647x; 1.0331x over previous
#include <cuda_runtime.h>
#include <cuda_bf16.h>
#include <math.h>
#include <string.h>

#define NPATH 11
#define DIMF  288
#define ZT    32
#define UVS   4
#define NT    256

static const int hc_l1[NPATH] = {0,1,2,0,1,1,2,0,1,2,2};
static const int hc_l2[NPATH] = {0,1,2,1,0,2,1,2,1,0,2};
static const int hc_lo[NPATH] = {0,0,0,1,1,1,1,2,2,2,2};

__device__ float g_C[NPATH][125];
__device__ float g_part[UVS][2048*DIMF];
__device__ __nv_bfloat16 g_wsp[NPATH*32*2*2048];   // pre-split W: [p][u][hi/lo][64row][32w]

// ---------------- host-side Wigner-3j (exact port of reference) ------------
static double hfact(int n){ double r=1.0; for(int i=2;i<=n;++i) r*=i; return r; }

static double h_su2(int j1,int m1,int j2,int m2,int j3,int m3){
  if (m1+m2 != m3) return 0.0;
  int vmin = -j1+j2+m3; if (-j1+m1 > vmin) vmin = -j1+m1; if (vmin < 0) vmin = 0;
  int vmax = j2+j3+m1; if (j3-j1+j2 < vmax) vmax = j3-j1+j2; if (j3+m3 < vmax) vmax = j3+m3;
  if (vmax < vmin) return 0.0;
  double C = sqrt((2.0*j3+1.0)
    * hfact(j3+j1-j2)*hfact(j3-j1+j2)*hfact(j1+j2-j3)*hfact(j3+m3)*hfact(j3-m3)
    / (hfact(j1+j2+j3+1)*hfact(j1-m1)*hfact(j1+m1)*hfact(j2-m2)*hfact(j2+m2)));
  double S = 0.0;
  for (int v = vmin; v <= vmax; ++v){
    double t = hfact(j2+j3+m1-v)*hfact(j1-m1+v)
             / (hfact(v)*hfact(j3-j1+j2-v)*hfact(j3+m3-v)*hfact(v+j1-j2-m3));
    S += ((v+j2+m2)&1) ? -t : t;
  }
  return C*S;
}

static void h_q(int l,int a,int b,double&re,double&im){
  double r=0.0,i=0.0; int m=a-l; const double s2=0.70710678118654752440;
  if (m<0){ if (b==l-m) r=s2; if (b==l+m) i=-s2; }
  else if (m==0){ if (b==l) r=1.0; }
  else { double s=(m&1)?-1.0:1.0; if (b==l+m) r=s*s2; if (b==l-m) i=s*s2; }
  if (l==1){ double t=r; r=i; i=-t; }
  else if (l==2){ r=-r; i=-i; }
  re=r; im=i;
}

static void compute_w3j_dense(float Cd[NPATH][125]){
  for (int p=0;p<NPATH;++p){
    int l1=hc_l1[p], l2=hc_l2[p], l3=hc_lo[p];
    int d1=2*l1+1, d2=2*l2+1, d3=2*l3+1;
    double cg[125]; for (int e=0;e<125;++e) cg[e]=0.0;
    for (int i=0;i<d1;++i) for (int k=0;k<d2;++k){
      int m1=i-l1, m2=k-l2;
      if (m1+m2 >= -l3 && m1+m2 <= l3)
        cg[(i*d2+k)*d3 + (l3+m1+m2)] = h_su2(l1,m1,l2,m2,l3,m1+m2);
    }
    double Cv[125]; double nrm=0.0;
    for (int jj=0;jj<d1;++jj) for (int ll=0;ll<d2;++ll) for (int mm=0;mm<d3;++mm){
      double cr=0.0;
      for (int i=0;i<d1;++i){
        double q1r,q1i; h_q(l1,i,jj,q1r,q1i);
        if (q1r==0.0 && q1i==0.0) continue;
        for (int k=0;k<d2;++k){
          double q2r,q2i; h_q(l2,k,ll,q2r,q2i);
          if (q2r==0.0 && q2i==0.0) continue;
          int n=(i-l1)+(k-l2)+l3;
          if (n<0 || n>=d3) continue;
          double g=cg[(i*d2+k)*d3+n];
          if (g==0.0) continue;
          double q3r,q3i; h_q(l3,n,mm,q3r,q3i); q3i=-q3i;
          double ar=q1r*q2r-q1i*q2i, ai=q1r*q2i+q1i*q2r;
          cr += g*(ar*q3r - ai*q3i);
        }
      }
      Cv[(jj*d2+ll)*d3+mm]=cr; nrm += cr*cr;
    }
    double inorm = 1.0/sqrt(nrm);
    for (int e=0;e<125;++e) Cd[p][e]=0.f;
    for (int e=0;e<d1*d2*d3;++e) Cd[p][e] = (float)(Cv[e]*inorm);
  }
}

// ---------------- device helpers -------------------------------------------
__device__ __forceinline__ unsigned smem_u32(const void* p){
  unsigned a;
  asm("{ .reg .u64 t; cvta.to.shared.u64 t, %1; cvt.u32.u64 %0, t; }" : "=r"(a) : "l"(p));
  return a;
}
__device__ __forceinline__ void ldsm4(unsigned* r, unsigned addr){
  asm volatile("ldmatrix.sync.aligned.m8n8.x4.shared.b16 {%0,%1,%2,%3}, [%4];"
    : "=r"(r[0]),"=r"(r[1]),"=r"(r[2]),"=r"(r[3]) : "r"(addr));
}
__device__ __forceinline__ void ldsm2t(unsigned* r, unsigned addr){
  asm volatile("ldmatrix.sync.aligned.m8n8.x2.trans.shared.b16 {%0,%1}, [%2];"
    : "=r"(r[0]),"=r"(r[1]) : "r"(addr));
}
__device__ __forceinline__ void mma_bf16(float* d, const unsigned* a, const unsigned* b){
  asm volatile("mma.sync.aligned.m16n8k16.row.col.f32.bf16.bf16.f32 "
    "{%0,%1,%2,%3}, {%4,%5,%6,%7}, {%8,%9}, {%0,%1,%2,%3};"
    : "+f"(d[0]),"+f"(d[1]),"+f"(d[2]),"+f"(d[3])
    : "r"(a[0]),"r"(a[1]),"r"(a[2]),"r"(a[3]), "r"(b[0]),"r"(b[1]));
}
__device__ __forceinline__ unsigned split_pack(float t){
  __nv_bfloat16 h = __float2bfloat16(t);
  float hf = __bfloat162float(h);
  float res = t - hf;
  unsigned r;
  asm("cvt.rn.bf16x2.f32 %0, %1, %2;" : "=r"(r) : "f"(res), "f"(hf));
  return r;
}

#define ASTR 144             // A row stride bytes (72 bf16), LDSM conflict-free
#define ATSZ (32*ASTR)       // 4608
#define ABUF (5*ATSZ)        // 23040 per buffer
#define BSTR 80              // B row stride bytes
#define BBUF (64*BSTR)       // 5120
// dynamic smem offsets
#define SA_OFF(b)  ((b)*ABUF)
#define SB1_OFF(b) (2*ABUF + (b)*BBUF)
#define SB2_OFF(b) (2*ABUF + 2*BBUF + (b)*BBUF)
#define SC_OFF     (2*ABUF + 4*BBUF)
#define DSM_BYTES  (SC_OFF + NPATH*125*4 + 16)

// ---------------- weight pre-split kernel -----------------------------------
__global__ void w_prep(const float* __restrict__ ws){
  int p = blockIdx.x >> 5, u = blockIdx.x & 31;
  int tid = threadIdx.x;
  __nv_bfloat16* b1 = g_wsp + ((size_t)(p*32+u)*2 + 0)*2048;
  __nv_bfloat16* b2 = g_wsp + ((size_t)(p*32+u)*2 + 1)*2048;
  #pragma unroll
  for (int r = 0; r < 4; ++r){
    int idx = r*256 + tid;
    int v = idx >> 5, w = idx & 31;
    float val = __ldg(ws + ((size_t)p*1024 + u*32 + v)*32 + w);
    __nv_bfloat16 h = __float2bfloat16(val);
    float res = val - __bfloat162float(h);
    __nv_bfloat16 l = __float2bfloat16(res);
    b1[(2*v  )*32 + w] = h;
    b1[(2*v+1)*32 + w] = h;
    b2[(2*v  )*32 + w] = l;
    b2[(2*v+1)*32 + w] = __ushort_as_bfloat16(0);
  }
}

// ---------------- per-path build + MMA (double-buffered) --------------------
template<int L1, int L2, int LO, int CB>
__device__ __forceinline__ void do_path(
    int p,
    const float* __restrict__ x1, const float* __restrict__ x2,
    float acc[9][4], const float* sC,
    unsigned char* dsm, unsigned aDSM,
    int zbase, int uvh, int tid, int lane, int zh, int nt)
{
  constexpr int D1 = 2*L1+1, D2 = 2*L2+1, K = 2*LO+1;
  constexpr int O1 = (L1==0)?0:((L1==1)?32:128);
  constexpr int O2 = (L2==0)?0:((L2==1)?32:128);
  const float* Cp = sC + p*125;

  const int z  = tid >> 3;
  const int vb = tid & 7;
  // hoist x2 loads: u-independent, reused across all 8 chunks
  float b[4][D2];
  {
    const float* x2p = x2 + (size_t)(zbase + z)*DIMF + O2;
    #pragma unroll
    for (int vi = 0; vi < 4; ++vi)
      #pragma unroll
      for (int j = 0; j < D2; ++j)
        b[vi][j] = __ldg(x2p + (vb*4 + vi)*D2 + j);
  }

  #pragma unroll 1
  for (int ch = 0; ch < 8; ++ch){
    const int u   = uvh*8 + ch;
    const int buf = ch & 1;
    unsigned char* sA  = dsm + SA_OFF(buf);
    unsigned char* sB1 = dsm + SB1_OFF(buf);
    unsigned char* sB2 = dsm + SB2_OFF(buf);
    // ---- prefetch pre-split weights (16B per thread per tile)
    const uint4* wsrc = (const uint4*)(g_wsp + (size_t)(p*32+u)*2*2048);
    uint4 w1 = __ldg(wsrc + tid);
    uint4 w2 = __ldg(wsrc + 256 + tid);
    // ---- build T via G-factorization: G[k][j] = sum_i C[i,j,k]*x1[i]
    {
      float a1[D1];
      const float* a1p = x1 + (size_t)(zbase + z)*DIMF + O1 + u*D1;
      #pragma unroll
      for (int i = 0; i < D1; ++i) a1[i] = __ldg(a1p + i);
      float G[K][D2];
      #pragma unroll
      for (int k = 0; k < K; ++k)
        #pragma unroll
        for (int j = 0; j < D2; ++j){
          float g = 0.f;
          #pragma unroll
          for (int i = 0; i < D1; ++i)
            g = fmaf(Cp[(i*D2+j)*K + k], a1[i], g);
          G[k][j] = g;
        }
      #pragma unroll
      for (int vi = 0; vi < 4; ++vi){
        int v = vb*4 + vi;
        float t[K];
        #pragma unroll
        for (int k = 0; k < K; ++k){
          float s = 0.f;
          #pragma unroll
          for (int j = 0; j < D2; ++j)
            s = fmaf(G[k][j], b[vi][j], s);
          t[k] = s;
        }
        #pragma unroll
        for (int k = 0; k < K; ++k)
          *(unsigned*)(sA + k*ATSZ + z*ASTR + v*4) = split_pack(t[k]);
      }
    }
    // ---- store staged weights (LDG latency hidden under build)
    {
      int row = tid >> 2, q = tid & 3;
      *(uint4*)(sB1 + row*BSTR + q*16) = w1;
      *(uint4*)(sB2 + row*BSTR + q*16) = w2;
    }
    __syncthreads();
    // ---- warp MMAs from buffer `buf`; next build may start before others finish
    unsigned aA  = aDSM + SA_OFF(buf);
    unsigned aB1 = aDSM + SB1_OFF(buf);
    unsigned aB2 = aDSM + SB2_OFF(buf);
    #pragma unroll
    for (int kb = 0; kb < 4; ++kb){
      unsigned bf1[2], bf2[2];
      unsigned brow = (unsigned)((kb*16 + (lane & 15))*BSTR + nt*16);
      ldsm2t(bf1, aB1 + brow);
      ldsm2t(bf2, aB2 + brow);
      #pragma unroll
      for (int k = 0; k < K; ++k){
        unsigned af[4];
        ldsm4(af, aA + (unsigned)(k*ATSZ + (zh*16 + (lane & 15))*ASTR
                                  + kb*32 + (lane >> 4)*16));
        mma_bf16(acc[CB + k], af, bf1);
        mma_bf16(acc[CB + k], af, bf2);
      }
    }
  }
}

// ---------------- main kernel ----------------------------------------------
__global__ void __launch_bounds__(NT, 2) tp_mma_kernel(
    const float* __restrict__ x1, const float* __restrict__ x2)
{
  extern __shared__ __align__(16) unsigned char dsm[];
  float* sC = (float*)(dsm + SC_OFF);

  const int tid  = threadIdx.x;
  const int lane = tid & 31;
  const int wid  = tid >> 5;
  const int zh   = wid >> 2;
  const int nt   = wid & 3;
  const int bid  = blockIdx.x;
  const int uvh  = bid & (UVS-1);
  const int zbase = (bid >> 2) * ZT;

  for (int e = tid; e < NPATH*125; e += NT)
    sC[e] = g_C[e/125][e%125];
  __syncthreads();

  unsigned aDSM = smem_u32(dsm);

  float acc[9][4];
  #pragma unroll
  for (int c = 0; c < 9; ++c)
    #pragma unroll
    for (int r = 0; r < 4; ++r) acc[c][r] = 0.f;

  do_path<0,0,0,0>( 0, x1,x2, acc,sC, dsm,aDSM, zbase,uvh,tid,lane,zh,nt);
  do_path<1,1,0,0>( 1, x1,x2, acc,sC, dsm,aDSM, zbase,uvh,tid,lane,zh,nt);
  do_path<2,2,0,0>( 2, x1,x2, acc,sC, dsm,aDSM, zbase,uvh,tid,lane,zh,nt);
  do_path<0,1,1,1>( 3, x1,x2, acc,sC, dsm,aDSM, zbase,uvh,tid,lane,zh,nt);
  do_path<1,0,1,1>( 4, x1,x2, acc,sC, dsm,aDSM, zbase,uvh,tid,lane,zh,nt);
  do_path<1,2,1,1>( 5, x1,x2, acc,sC, dsm,aDSM, zbase,uvh,tid,lane,zh,nt);
  do_path<2,1,1,1>( 6, x1,x2, acc,sC, dsm,aDSM, zbase,uvh,tid,lane,zh,nt);
  do_path<0,2,2,4>( 7, x1,x2, acc,sC, dsm,aDSM, zbase,uvh,tid,lane,zh,nt);
  do_path<1,1,2,4>( 8, x1,x2, acc,sC, dsm,aDSM, zbase,uvh,tid,lane,zh,nt);
  do_path<2,0,2,4>( 9, x1,x2, acc,sC, dsm,aDSM, zbase,uvh,tid,lane,zh,nt);
  do_path<2,2,2,4>(10, x1,x2, acc,sC, dsm,aDSM, zbase,uvh,tid,lane,zh,nt);

  const float A0f = 0.01804219591217583f;   // sqrt(1/3072)
  const float A1f = 0.02706329386826371f;   // sqrt(3)/64
  const float A2f = 0.03493856214843422f;   // sqrt(5)/64

  int r0 = zh*16 + (lane >> 2);
  int c0 = nt*8 + (lane & 3)*2;
  float* b0 = g_part[uvh] + (size_t)(zbase + r0)     * DIMF;
  float* b1 = g_part[uvh] + (size_t)(zbase + r0 + 8) * DIMF;

  b0[c0]   = A0f*acc[0][0];  b0[c0+1] = A0f*acc[0][1];
  b1[c0]   = A0f*acc[0][2];  b1[c0+1] = A0f*acc[0][3];
  #pragma unroll
  for (int c = 0; c < 3; ++c){
    b0[32 + c0*3 + c]     = A1f*acc[1+c][0];
    b0[32 + (c0+1)*3 + c] = A1f*acc[1+c][1];
    b1[32 + c0*3 + c]     = A1f*acc[1+c][2];
    b1[32 + (c0+1)*3 + c] = A1f*acc[1+c][3];
  }
  #pragma unroll
  for (int c = 0; c < 5; ++c){
    b0[128 + c0*5 + c]     = A2f*acc[4+c][0];
    b0[128 + (c0+1)*5 + c] = A2f*acc[4+c][1];
    b1[128 + c0*5 + c]     = A2f*acc[4+c][2];
    b1[128 + (c0+1)*5 + c] = A2f*acc[4+c][3];
  }
}

__global__ void reduce_kernel(float* __restrict__ out){
  int i = blockIdx.x * blockDim.x + threadIdx.x;
  float4 r = make_float4(0.f, 0.f, 0.f, 0.f);
  #pragma unroll
  for (int s = 0; s < UVS; ++s){
    float4 a = ((const float4*)g_part[s])[i];
    r.x += a.x; r.y += a.y; r.z += a.z; r.w += a.w;
  }
  ((float4*)out)[i] = r;
}

extern "C" void kernel_launch(void* const* d_in, const int* in_sizes, int n_in,
                              void* d_out, int out_size) {
  const float* x1 = (const float*)d_in[0];
  const float* x2 = (const float*)d_in[1];
  const float* ws = (const float*)d_in[2];
  float* out = (float*)d_out;
  (void)in_sizes; (void)n_in; (void)out_size;

  static float h_C[NPATH][125];
  compute_w3j_dense(h_C);
  cudaMemcpyToSymbolAsync(g_C, h_C, sizeof(h_C), 0, cudaMemcpyHostToDevice, 0);

  static int smem_set = 0;
  if (!smem_set){
    cudaFuncSetAttribute(tp_mma_kernel,
                         cudaFuncAttributeMaxDynamicSharedMemorySize, DSM_BYTES);
    smem_set = 1;
  }
  w_prep<<<NPATH*32, 256>>>(ws);
  tp_mma_kernel<<<(2048/ZT)*UVS, NT, DSM_BYTES>>>(x1, x2);
  reduce_kernel<<<(2048*DIMF/4)/256, 256>>>(out);
}